// round 15
// baseline (speedup 1.0000x reference)
#include <cuda_runtime.h>
#include <cuda_bf16.h>
#include <math.h>

// Problem constants
#define B      32
#define CIN    512
#define HW     4096          // 64*64
#define MID    32            // 512/16
#define COUT   512

#define ROWS_PER_CTA   4
#define GRID_CTAS      (B * CIN / ROWS_PER_CTA)   // 4096
#define CTAS_PER_BATCH (CIN / ROWS_PER_CTA)       // 128
#define CNT_PAD        32                         // 128B -> private L2 line

// Scratch (no cudaMalloc allowed)
__device__ float        g_pooled[B * CIN];      // [B, CIN] means
__device__ unsigned int g_cnt[B * CNT_PAD];     // per-batch arrive counters

// acq_rel fetch-add: release (publishes this CTA's mean stores, ordered by the
// preceding __syncthreads) + acquire (the winner sees all other CTAs' means).
__device__ __forceinline__ unsigned int atom_acqrel_add(unsigned int* p) {
    unsigned int v;
    asm volatile("atom.acq_rel.gpu.global.add.u32 %0, [%1], 1;"
                 : "=r"(v) : "l"(p) : "memory");
    return v;
}

// ---------------------------------------------------------------------------
// Fused kernel, v5: amortized arrivals + last-CTA epilogue (no spinners).
//  Every CTA pools 4 contiguous rows (one batch), stores 4 means (st.cg),
//  then ONE acq_rel fetch-add on its batch counter. The 128th arriver of a
//  batch performs that batch's FC chain inline (phase1 8wx4 mids, phase2
//  8wx64 outputs via coalesced L2-hot w2 + butterflies), then resets the
//  counter for the next graph replay.
// ---------------------------------------------------------------------------
__global__ __launch_bounds__(256, 8) void se_onekernel(
    const float* __restrict__ x,
    const float* __restrict__ w1, const float* __restrict__ b1,
    const float* __restrict__ w2, const float* __restrict__ b2,
    float* __restrict__ out)
{
    const int tid  = threadIdx.x;
    const int lane = tid & 31;
    const int wid  = tid >> 5;

    __shared__ float    warp_sums[8][4];
    __shared__ float    s_pooled[CIN];
    __shared__ float    s_h[MID];
    __shared__ unsigned s_last;

    const int row_base = blockIdx.x * ROWS_PER_CTA;   // 4 rows, same batch
    const int b        = row_base >> 9;               // batch index

    // ---------------- Pool: 4 rows, 64KB contiguous ----------------
    {
        const float4* __restrict__ p =
            reinterpret_cast<const float4*>(x + (size_t)row_base * HW);

        float a0, a1, a2, a3;
        {
            float4 u0 = p[tid],       u1 = p[tid + 256];
            float4 u2 = p[tid + 512], u3 = p[tid + 768];
            a0 = (u0.x + u0.y) + (u0.z + u0.w) + (u1.x + u1.y) + (u1.z + u1.w)
               + (u2.x + u2.y) + (u2.z + u2.w) + (u3.x + u3.y) + (u3.z + u3.w);
        }
        {
            float4 u0 = p[1024 + tid],       u1 = p[1024 + tid + 256];
            float4 u2 = p[1024 + tid + 512], u3 = p[1024 + tid + 768];
            a1 = (u0.x + u0.y) + (u0.z + u0.w) + (u1.x + u1.y) + (u1.z + u1.w)
               + (u2.x + u2.y) + (u2.z + u2.w) + (u3.x + u3.y) + (u3.z + u3.w);
        }
        {
            float4 u0 = p[2048 + tid],       u1 = p[2048 + tid + 256];
            float4 u2 = p[2048 + tid + 512], u3 = p[2048 + tid + 768];
            a2 = (u0.x + u0.y) + (u0.z + u0.w) + (u1.x + u1.y) + (u1.z + u1.w)
               + (u2.x + u2.y) + (u2.z + u2.w) + (u3.x + u3.y) + (u3.z + u3.w);
        }
        {
            float4 u0 = p[3072 + tid],       u1 = p[3072 + tid + 256];
            float4 u2 = p[3072 + tid + 512], u3 = p[3072 + tid + 768];
            a3 = (u0.x + u0.y) + (u0.z + u0.w) + (u1.x + u1.y) + (u1.z + u1.w)
               + (u2.x + u2.y) + (u2.z + u2.w) + (u3.x + u3.y) + (u3.z + u3.w);
        }

        #pragma unroll
        for (int off = 16; off > 0; off >>= 1) {
            a0 += __shfl_xor_sync(0xFFFFFFFFu, a0, off);
            a1 += __shfl_xor_sync(0xFFFFFFFFu, a1, off);
            a2 += __shfl_xor_sync(0xFFFFFFFFu, a2, off);
            a3 += __shfl_xor_sync(0xFFFFFFFFu, a3, off);
        }
        if (lane == 0) {
            warp_sums[wid][0] = a0;  warp_sums[wid][1] = a1;
            warp_sums[wid][2] = a2;  warp_sums[wid][3] = a3;
        }
        __syncthreads();

        // warps 0..3 finalize one row each
        if (wid < 4) {
            float t = (lane < 8) ? warp_sums[lane][wid] : 0.0f;
            #pragma unroll
            for (int off = 4; off > 0; off >>= 1)
                t += __shfl_xor_sync(0xFFFFFFFFu, t, off);
            if (lane == 0)
                __stcg(&g_pooled[row_base + wid], t * (1.0f / (float)HW));
        }
        __syncthreads();     // order the 4 mean stores before the release-atomic
    }

    // ---------------- Arrive; 128th arriver does the batch FC ----------------
    if (tid == 0) {
        unsigned int old = atom_acqrel_add(&g_cnt[b * CNT_PAD]);
        s_last = (old == (unsigned)(CTAS_PER_BATCH - 1)) ? 1u : 0u;
        if (s_last) g_cnt[b * CNT_PAD] = 0u;   // reset for next replay
    }
    __syncthreads();
    if (!s_last) return;

    // ---------------- FC for batch b (proven v4 code, L2-hot) ----------------
    s_pooled[tid]       = __ldcg(&g_pooled[b * CIN + tid]);
    s_pooled[tid + 256] = __ldcg(&g_pooled[b * CIN + tid + 256]);
    __syncthreads();

    // Phase 1: warp wid computes mids {4*wid .. 4*wid+3}
    {
        const int m0 = wid * 4;
        const float* __restrict__ w1r0 = w1 + (size_t)(m0 + 0) * CIN;
        const float* __restrict__ w1r1 = w1 + (size_t)(m0 + 1) * CIN;
        const float* __restrict__ w1r2 = w1 + (size_t)(m0 + 2) * CIN;
        const float* __restrict__ w1r3 = w1 + (size_t)(m0 + 3) * CIN;

        float a0 = 0.f, a1 = 0.f, a2 = 0.f, a3 = 0.f;
        #pragma unroll
        for (int j = 0; j < 16; j++) {
            const int k = lane + 32 * j;
            const float pv = s_pooled[k];
            a0 = fmaf(pv, __ldg(w1r0 + k), a0);
            a1 = fmaf(pv, __ldg(w1r1 + k), a1);
            a2 = fmaf(pv, __ldg(w1r2 + k), a2);
            a3 = fmaf(pv, __ldg(w1r3 + k), a3);
        }
        #pragma unroll
        for (int off = 16; off > 0; off >>= 1) {
            a0 += __shfl_xor_sync(0xFFFFFFFFu, a0, off);
            a1 += __shfl_xor_sync(0xFFFFFFFFu, a1, off);
            a2 += __shfl_xor_sync(0xFFFFFFFFu, a2, off);
            a3 += __shfl_xor_sync(0xFFFFFFFFu, a3, off);
        }
        if (lane == 0) {
            float h0 = a0 + __ldg(b1 + m0 + 0);
            float h1 = a1 + __ldg(b1 + m0 + 1);
            float h2 = a2 + __ldg(b1 + m0 + 2);
            float h3 = a3 + __ldg(b1 + m0 + 3);
            s_h[m0 + 0] = h0 > 0.f ? h0 : 0.f;
            s_h[m0 + 1] = h1 > 0.f ? h1 : 0.f;
            s_h[m0 + 2] = h2 > 0.f ? h2 : 0.f;
            s_h[m0 + 3] = h3 > 0.f ? h3 : 0.f;
        }
    }
    __syncthreads();

    // Phase 2: warp wid owns outputs [64*wid, 64*wid+64).
    {
        const int obase = wid * 64;
        const float hv  = s_h[lane];
        float res0 = 0.0f, res1 = 0.0f;

        #pragma unroll
        for (int i = 0; i < 32; i++) {
            float r0 = __ldg(&w2[(size_t)(obase + i)      * MID + lane]);
            float r1 = __ldg(&w2[(size_t)(obase + 32 + i) * MID + lane]);
            float p0 = r0 * hv;
            float p1 = r1 * hv;
            #pragma unroll
            for (int off = 16; off > 0; off >>= 1) {
                p0 += __shfl_xor_sync(0xFFFFFFFFu, p0, off);
                p1 += __shfl_xor_sync(0xFFFFFFFFu, p1, off);
            }
            if (lane == i) { res0 = p0; res1 = p1; }
        }

        const int o0 = obase + lane;
        const int o1 = obase + 32 + lane;
        float acc0 = res0 + __ldg(b2 + o0);
        float acc1 = res1 + __ldg(b2 + o1);
        out[(size_t)b * COUT + o0] = 1.0f / (1.0f + __expf(-acc0));
        out[(size_t)b * COUT + o1] = 1.0f / (1.0f + __expf(-acc1));
    }
}

// ---------------------------------------------------------------------------
extern "C" void kernel_launch(void* const* d_in, const int* in_sizes, int n_in,
                              void* d_out, int out_size) {
    const float* x  = (const float*)d_in[0];
    const float* w1 = (const float*)d_in[1];
    const float* b1 = (const float*)d_in[2];
    const float* w2 = (const float*)d_in[3];
    const float* b2 = (const float*)d_in[4];
    float* out = (float*)d_out;

    se_onekernel<<<GRID_CTAS, 256>>>(x, w1, b1, w2, b2, out);
}

// round 16
// speedup vs baseline: 1.0756x; 1.0756x over previous
#include <cuda_runtime.h>
#include <cuda_bf16.h>
#include <math.h>

// Problem constants
#define B     32
#define CIN   512
#define HW    4096          // 64*64
#define MID   32            // 512/16
#define COUT  512

#define POOL_CTAS (B * CIN)   // 16384

// Scratch (no cudaMalloc allowed)
__device__ float g_pooled[B * CIN];   // [B, CIN] means

__device__ __forceinline__ void l2_prefetch(const void* p) {
    asm volatile("prefetch.global.L2 [%0];" :: "l"(p));
}

// ---------------------------------------------------------------------------
// Kernel 1: global average pool (proven 6.9 TB/s shape: 1 row/CTA, 256 thr,
// 4x float4 front-loaded, tree reduce). NEW: the last 8 CTAs (scheduled in
// the final wave) prefetch all of w1/w2/b1/b2 into L2 after their pool work,
// so the fc kernel's weight reads are L2 hits instead of cold DRAM misses.
// ---------------------------------------------------------------------------
__global__ __launch_bounds__(256) void se_pool_kernel(
    const float* __restrict__ x,
    const float* __restrict__ w1, const float* __restrict__ w2,
    const float* __restrict__ b1, const float* __restrict__ b2)
{
    const int row = blockIdx.x;                 // 0 .. B*CIN-1
    const float4* __restrict__ p =
        reinterpret_cast<const float4*>(x + (size_t)row * HW);
    const int tid = threadIdx.x;

    float4 v0 = p[tid];
    float4 v1 = p[tid + 256];
    float4 v2 = p[tid + 512];
    float4 v3 = p[tid + 768];

    float s = (v0.x + v0.y) + (v0.z + v0.w)
            + (v1.x + v1.y) + (v1.z + v1.w)
            + (v2.x + v2.y) + (v2.z + v2.w)
            + (v3.x + v3.y) + (v3.z + v3.w);

    #pragma unroll
    for (int off = 16; off > 0; off >>= 1)
        s += __shfl_xor_sync(0xFFFFFFFFu, s, off);

    __shared__ float warp_sums[8];
    const int lane = tid & 31;
    const int wid  = tid >> 5;
    if (lane == 0) warp_sums[wid] = s;
    __syncthreads();

    if (wid == 0) {
        float t = (lane < 8) ? warp_sums[lane] : 0.0f;
        #pragma unroll
        for (int off = 4; off > 0; off >>= 1)
            t += __shfl_xor_sync(0xFFFFFFFFu, t, off);
        if (lane == 0)
            g_pooled[row] = t * (1.0f / (float)HW);
    }

    // Last-wave CTAs: warm L2 with the FC weights (128KB = 1024 lines of 128B).
    // 8 CTAs x 256 threads: thread t of each prefetches 2 w1 lines + 2 w2 lines.
    if (row >= POOL_CTAS - 8) {
        const char* w1c = (const char*)w1;
        const char* w2c = (const char*)w2;
        l2_prefetch(w1c + (size_t)tid * 128);
        l2_prefetch(w1c + (size_t)(tid + 256) * 128);
        l2_prefetch(w2c + (size_t)tid * 128);
        l2_prefetch(w2c + (size_t)(tid + 256) * 128);
        if (tid < 8)  l2_prefetch((const char*)b1 + tid * 16);
        if (tid < 16) l2_prefetch((const char*)b2 + tid * 128);
    }
}

// ---------------------------------------------------------------------------
// Kernel 2: FC bottleneck + ReLU, FC expansion + sigmoid. (R3 proven shape;
// weights now L2-hot thanks to the pool-side prefetch.)
// One CTA per batch row b. 512 threads (16 warps).
//   Phase 1: warp w computes mids {2w, 2w+1} (coalesced w1, 2 accumulators).
//   Phase 2: warp w owns outputs [32w, +32): coalesced w2 loads + butterfly.
// ---------------------------------------------------------------------------
__global__ __launch_bounds__(512) void se_fc_kernel(
    const float* __restrict__ w1, const float* __restrict__ b1,
    const float* __restrict__ w2, const float* __restrict__ b2,
    float* __restrict__ out)
{
    const int b    = blockIdx.x;
    const int tid  = threadIdx.x;
    const int lane = tid & 31;
    const int wid  = tid >> 5;

    __shared__ float s_pooled[CIN];
    __shared__ float s_h[MID];

    s_pooled[tid] = g_pooled[b * CIN + tid];
    __syncthreads();

    // Phase 1: each of 16 warps computes 2 mid channels
    {
        const int m0 = wid * 2;
        const float* __restrict__ w1r0 = w1 + (size_t)(m0 + 0) * CIN;
        const float* __restrict__ w1r1 = w1 + (size_t)(m0 + 1) * CIN;

        float a0 = 0.f, a1 = 0.f;
        #pragma unroll
        for (int j = 0; j < 16; j++) {
            const int k = lane + 32 * j;
            const float pv = s_pooled[k];
            a0 = fmaf(pv, __ldg(w1r0 + k), a0);
            a1 = fmaf(pv, __ldg(w1r1 + k), a1);
        }
        #pragma unroll
        for (int off = 16; off > 0; off >>= 1) {
            a0 += __shfl_xor_sync(0xFFFFFFFFu, a0, off);
            a1 += __shfl_xor_sync(0xFFFFFFFFu, a1, off);
        }
        if (lane == 0) {
            float h0 = a0 + __ldg(b1 + m0 + 0);
            float h1 = a1 + __ldg(b1 + m0 + 1);
            s_h[m0 + 0] = h0 > 0.f ? h0 : 0.f;
            s_h[m0 + 1] = h1 > 0.f ? h1 : 0.f;
        }
    }
    __syncthreads();

    // Phase 2: warp wid owns outputs [32*wid, 32*wid+32)
    {
        const int o_base = wid * 32;
        const float hv   = s_h[lane];
        float res = 0.0f;

        #pragma unroll
        for (int i = 0; i < 32; i++) {
            float r = __ldg(&w2[(size_t)(o_base + i) * MID + lane]);  // coalesced, L2-hot
            float p = r * hv;
            #pragma unroll
            for (int off = 16; off > 0; off >>= 1)
                p += __shfl_xor_sync(0xFFFFFFFFu, p, off);
            if (lane == i) res = p;
        }

        const int o = o_base + lane;
        float acc = res + __ldg(b2 + o);
        out[(size_t)b * COUT + o] = 1.0f / (1.0f + __expf(-acc));
    }
}

// ---------------------------------------------------------------------------
extern "C" void kernel_launch(void* const* d_in, const int* in_sizes, int n_in,
                              void* d_out, int out_size) {
    const float* x  = (const float*)d_in[0];
    const float* w1 = (const float*)d_in[1];
    const float* b1 = (const float*)d_in[2];
    const float* w2 = (const float*)d_in[3];
    const float* b2 = (const float*)d_in[4];
    float* out = (float*)d_out;

    se_pool_kernel<<<POOL_CTAS, 256>>>(x, w1, w2, b1, b2);
    se_fc_kernel<<<B, 512>>>(w1, b1, w2, b2, out);
}

// round 17
// speedup vs baseline: 1.1413x; 1.0611x over previous
#include <cuda_runtime.h>
#include <cuda_bf16.h>
#include <math.h>

// Problem constants
#define B     32
#define CIN   512
#define HW    4096          // 64*64
#define MID   32            // 512/16
#define COUT  512

#define POOL_CTAS   (B * CIN)   // 16384
#define FC_PER_B    4
#define FC_CTAS     (B * FC_PER_B)   // 128

// Scratch (no cudaMalloc allowed)
__device__ float g_pooled[B * CIN];   // [B, CIN] means

// ---------------------------------------------------------------------------
// Kernel 1: global average pool (proven 6.9 TB/s shape), now with streaming
// (evict-first) loads: x is single-use; keep L2 clean for means + weights.
// ---------------------------------------------------------------------------
__global__ __launch_bounds__(256) void se_pool_kernel(const float* __restrict__ x) {
    const int row = blockIdx.x;                 // 0 .. B*CIN-1
    const float4* __restrict__ p =
        reinterpret_cast<const float4*>(x + (size_t)row * HW);
    const int tid = threadIdx.x;

    float4 v0 = __ldcs(p + tid);
    float4 v1 = __ldcs(p + tid + 256);
    float4 v2 = __ldcs(p + tid + 512);
    float4 v3 = __ldcs(p + tid + 768);

    float s = (v0.x + v0.y) + (v0.z + v0.w)
            + (v1.x + v1.y) + (v1.z + v1.w)
            + (v2.x + v2.y) + (v2.z + v2.w)
            + (v3.x + v3.y) + (v3.z + v3.w);

    #pragma unroll
    for (int off = 16; off > 0; off >>= 1)
        s += __shfl_xor_sync(0xFFFFFFFFu, s, off);

    __shared__ float warp_sums[8];
    const int lane = tid & 31;
    const int wid  = tid >> 5;
    if (lane == 0) warp_sums[wid] = s;
    __syncthreads();

    if (wid == 0) {
        float t = (lane < 8) ? warp_sums[lane] : 0.0f;
        #pragma unroll
        for (int off = 4; off > 0; off >>= 1)
            t += __shfl_xor_sync(0xFFFFFFFFu, t, off);
        if (lane == 0)
            g_pooled[row] = t * (1.0f / (float)HW);
    }
}

// ---------------------------------------------------------------------------
// Kernel 2: FC chain, 128 CTAs (4 per batch) x 256 threads (8 warps).
//  CTA (b, q): batch b = blockIdx/4, output quarter q = blockIdx%4.
//  Phase 1 (duplicated per CTA, cheap): warp w computes mids {4w..4w+3}.
//  Phase 2: warp w owns 16 outputs [q*128 + 16w, +16): coalesced w2 loads +
//           16 butterfly chains (half the R3 chain count, 4x the CTAs).
// ---------------------------------------------------------------------------
__global__ __launch_bounds__(256) void se_fc_kernel(
    const float* __restrict__ w1, const float* __restrict__ b1,
    const float* __restrict__ w2, const float* __restrict__ b2,
    float* __restrict__ out)
{
    const int b    = blockIdx.x >> 2;
    const int q    = blockIdx.x & 3;
    const int tid  = threadIdx.x;
    const int lane = tid & 31;
    const int wid  = tid >> 5;

    __shared__ float s_pooled[CIN];
    __shared__ float s_h[MID];

    s_pooled[tid]       = g_pooled[b * CIN + tid];
    s_pooled[tid + 256] = g_pooled[b * CIN + tid + 256];
    __syncthreads();

    // Phase 1: warp wid computes mids {4*wid .. 4*wid+3}
    {
        const int m0 = wid * 4;
        const float* __restrict__ w1r0 = w1 + (size_t)(m0 + 0) * CIN;
        const float* __restrict__ w1r1 = w1 + (size_t)(m0 + 1) * CIN;
        const float* __restrict__ w1r2 = w1 + (size_t)(m0 + 2) * CIN;
        const float* __restrict__ w1r3 = w1 + (size_t)(m0 + 3) * CIN;

        float a0 = 0.f, a1 = 0.f, a2 = 0.f, a3 = 0.f;
        #pragma unroll
        for (int j = 0; j < 16; j++) {
            const int k = lane + 32 * j;
            const float pv = s_pooled[k];
            a0 = fmaf(pv, __ldg(w1r0 + k), a0);
            a1 = fmaf(pv, __ldg(w1r1 + k), a1);
            a2 = fmaf(pv, __ldg(w1r2 + k), a2);
            a3 = fmaf(pv, __ldg(w1r3 + k), a3);
        }
        #pragma unroll
        for (int off = 16; off > 0; off >>= 1) {
            a0 += __shfl_xor_sync(0xFFFFFFFFu, a0, off);
            a1 += __shfl_xor_sync(0xFFFFFFFFu, a1, off);
            a2 += __shfl_xor_sync(0xFFFFFFFFu, a2, off);
            a3 += __shfl_xor_sync(0xFFFFFFFFu, a3, off);
        }
        if (lane == 0) {
            float h0 = a0 + __ldg(b1 + m0 + 0);
            float h1 = a1 + __ldg(b1 + m0 + 1);
            float h2 = a2 + __ldg(b1 + m0 + 2);
            float h3 = a3 + __ldg(b1 + m0 + 3);
            s_h[m0 + 0] = h0 > 0.f ? h0 : 0.f;
            s_h[m0 + 1] = h1 > 0.f ? h1 : 0.f;
            s_h[m0 + 2] = h2 > 0.f ? h2 : 0.f;
            s_h[m0 + 3] = h3 > 0.f ? h3 : 0.f;
        }
    }
    __syncthreads();

    // Phase 2: warp wid owns 16 outputs [q*128 + 16*wid, +16)
    {
        const int obase = q * 128 + wid * 16;
        const float hv  = s_h[lane];
        float res = 0.0f;

        #pragma unroll
        for (int i = 0; i < 16; i++) {
            float r = __ldg(&w2[(size_t)(obase + i) * MID + lane]);  // coalesced
            float p = r * hv;
            #pragma unroll
            for (int off = 16; off > 0; off >>= 1)
                p += __shfl_xor_sync(0xFFFFFFFFu, p, off);
            if (lane == i) res = p;          // lanes 0..15 keep outputs
        }

        if (lane < 16) {
            const int o = obase + lane;
            float acc = res + __ldg(b2 + o);
            out[(size_t)b * COUT + o] = 1.0f / (1.0f + __expf(-acc));
        }
    }
}

// ---------------------------------------------------------------------------
extern "C" void kernel_launch(void* const* d_in, const int* in_sizes, int n_in,
                              void* d_out, int out_size) {
    const float* x  = (const float*)d_in[0];
    const float* w1 = (const float*)d_in[1];
    const float* b1 = (const float*)d_in[2];
    const float* w2 = (const float*)d_in[3];
    const float* b2 = (const float*)d_in[4];
    float* out = (float*)d_out;

    se_pool_kernel<<<POOL_CTAS, 256>>>(x);
    se_fc_kernel<<<FC_CTAS, 256>>>(w1, b1, w2, b2, out);
}